// round 3
// baseline (speedup 1.0000x reference)
#include <cuda_runtime.h>

// TPLoss: pred [4096, 8192] f32, labels [4096, 8192] i32 (0/1)
// sigmoid p; TP_b = sum(p*l); with l in {0,1}:
//   1 - TP - TN = 1 - N + Sp + Sl - 2*TP
// out_b = TP / (1 - TP - TN);  loss = -mean(out_b)
// Single fused kernel; 2-stage software-pipelined loads for sustained MLP.

#define B_ROWS 4096
#define N_COLS 8192
#define VEC (N_COLS / 4)        // 2048 float4 per row
#define THREADS 256
#define ITERS (VEC / THREADS)   // 8

__device__ float        g_row_out[B_ROWS];
__device__ unsigned int g_done = 0;   // reset by last block each launch

// sigmoid via single MUFU: sigmoid(x) = 0.5*tanh(0.5*x) + 0.5
__device__ __forceinline__ float fast_sigmoid(float x) {
    float t;
    asm("tanh.approx.f32 %0, %1;" : "=f"(t) : "f"(x * 0.5f));
    return fmaf(t, 0.5f, 0.5f);
}

__global__ __launch_bounds__(THREADS)
void tploss_fused_kernel(const float4* __restrict__ pred,
                         const int4*  __restrict__ labels,
                         float* __restrict__ out) {
    const int b = blockIdx.x;
    const float4* p = pred   + (size_t)b * VEC + threadIdx.x;
    const int4*   l = labels + (size_t)b * VEC + threadIdx.x;

    float sp = 0.f;   // sum sigmoid
    float tp = 0.f;   // sum sigmoid * label
    int   cnt = 0;    // sum label

    // 2-stage software pipeline: always >=2 independent LDG.128 pairs in flight
    float4 x0 = __ldcs(p);
    int4   y0 = __ldcs(l);

    #pragma unroll
    for (int k = 0; k < ITERS - 1; k++) {
        float4 x1 = __ldcs(p + (k + 1) * THREADS);
        int4   y1 = __ldcs(l + (k + 1) * THREADS);

        float s0 = fast_sigmoid(x0.x);
        float s1 = fast_sigmoid(x0.y);
        float s2 = fast_sigmoid(x0.z);
        float s3 = fast_sigmoid(x0.w);
        sp += (s0 + s1) + (s2 + s3);
        tp += (y0.x ? s0 : 0.f) + (y0.y ? s1 : 0.f)
            + (y0.z ? s2 : 0.f) + (y0.w ? s3 : 0.f);
        cnt += y0.x + y0.y + y0.z + y0.w;

        x0 = x1; y0 = y1;
    }
    {   // epilogue iteration
        float s0 = fast_sigmoid(x0.x);
        float s1 = fast_sigmoid(x0.y);
        float s2 = fast_sigmoid(x0.z);
        float s3 = fast_sigmoid(x0.w);
        sp += (s0 + s1) + (s2 + s3);
        tp += (y0.x ? s0 : 0.f) + (y0.y ? s1 : 0.f)
            + (y0.z ? s2 : 0.f) + (y0.w ? s3 : 0.f);
        cnt += y0.x + y0.y + y0.z + y0.w;
    }

    // warp reduce 3 accumulators
    #pragma unroll
    for (int off = 16; off > 0; off >>= 1) {
        sp  += __shfl_down_sync(0xffffffffu, sp,  off);
        tp  += __shfl_down_sync(0xffffffffu, tp,  off);
        cnt += __shfl_down_sync(0xffffffffu, cnt, off);
    }

    __shared__ float s_sp[THREADS / 32];
    __shared__ float s_tp[THREADS / 32];
    __shared__ int   s_cnt[THREADS / 32];
    const int lane = threadIdx.x & 31;
    const int wid  = threadIdx.x >> 5;
    if (lane == 0) { s_sp[wid] = sp; s_tp[wid] = tp; s_cnt[wid] = cnt; }
    __syncthreads();

    __shared__ bool s_is_last;
    if (threadIdx.x == 0) {
        float fsp = 0.f, ftp = 0.f; int fc = 0;
        #pragma unroll
        for (int w = 0; w < THREADS / 32; w++) {
            fsp += s_sp[w]; ftp += s_tp[w]; fc += s_cnt[w];
        }
        float denom = 1.0f - (float)N_COLS + fsp + (float)fc - 2.0f * ftp;
        g_row_out[b] = ftp / denom;
        __threadfence();
        unsigned int prev = atomicAdd(&g_done, 1u);
        s_is_last = (prev == (unsigned int)(gridDim.x - 1));
    }
    __syncthreads();

    if (s_is_last) {
        __threadfence();  // acquire: make all g_row_out writes visible
        float acc = 0.f;
        #pragma unroll 16
        for (int i = threadIdx.x; i < B_ROWS; i += THREADS)
            acc += g_row_out[i];

        #pragma unroll
        for (int off = 16; off > 0; off >>= 1)
            acc += __shfl_down_sync(0xffffffffu, acc, off);

        __shared__ float s_fin[THREADS / 32];
        if (lane == 0) s_fin[wid] = acc;
        __syncthreads();
        if (threadIdx.x == 0) {
            float tot = 0.f;
            #pragma unroll
            for (int w = 0; w < THREADS / 32; w++) tot += s_fin[w];
            out[0] = -tot / (float)B_ROWS;
            g_done = 0;   // reset for next graph replay
        }
    }
}

extern "C" void kernel_launch(void* const* d_in, const int* in_sizes, int n_in,
                              void* d_out, int out_size) {
    const float4* pred   = (const float4*)d_in[0];
    const int4*   labels = (const int4*)d_in[1];
    float* out = (float*)d_out;

    tploss_fused_kernel<<<B_ROWS, THREADS>>>(pred, labels, out);
}